// round 4
// baseline (speedup 1.0000x reference)
#include <cuda_runtime.h>
#include <cstdint>

#define B_    256
#define N_    32
#define DH_   128
#define E_    496
#define KH    256     // DIM_HID
#define NO    96      // DIM_OUT
#define AOUT  12
#define ETILE 62      // edges per block (496 = 8*62)
#define MROWS 128     // 2*ETILE=124 padded to 128
#define LDH   257     // hs row pitch (bank-conflict-free for tm stride 4*257%32=4)
#define LDP   97      // P row pitch
#define JTILE 64
#define LDW1  257

// -------- device scratch (no allocation allowed) --------
__device__ float g_u[2u * B_ * N_ * KH];   // [s][b][n][k], 16 MB
__device__ float g_w2t[KH * NO];           // W2 transposed to [k][n]
__device__ int   g_ef[E_], g_et[E_];

// -------- f32x2 helpers --------
__device__ __forceinline__ unsigned long long pk2(float x) {
    unsigned long long r;
    asm("mov.b64 %0, {%1,%2};" : "=l"(r) : "f"(x), "f"(x));
    return r;
}
__device__ __forceinline__ void ffma2(unsigned long long& d,
                                      unsigned long long a,
                                      unsigned long long b) {
    asm("fma.rn.f32x2 %0, %1, %2, %0;" : "+l"(d) : "l"(a), "l"(b));
}
__device__ __forceinline__ float2 upk(unsigned long long v) {
    float2 r;
    asm("mov.b64 {%0,%1}, %2;" : "=f"(r.x), "=f"(r.y) : "l"(v));
    return r;
}

// -------- prep: normalize edge dtype (int32 vs int64) --------
__global__ void prep_edges(const int* __restrict__ efw, const int* __restrict__ etw) {
    int bad = 0;
    // words 0..E_-1 are in-bounds for both int32 (E_ words) and int64 (2E_ words)
    for (int t = threadIdx.x; t < E_; t += blockDim.x)
        if (t & 1)
            if (efw[t] != 0 || etw[t] != 0) bad = 1;
    int is32 = __syncthreads_or(bad);   // any nonzero odd word => int32
    for (int e = threadIdx.x; e < E_; e += blockDim.x) {
        g_ef[e] = is32 ? efw[e] : efw[2 * e];
        g_et[e] = is32 ? etw[e] : etw[2 * e];
    }
}

// -------- prep: transpose W2 [n][k] -> [k][n] (tiny, 98 KB) --------
__global__ void transpose_w2(const float* __restrict__ W2) {
    int idx = blockIdx.x * 256 + threadIdx.x;   // 0..24575
    if (idx < KH * NO) {
        int k = idx / NO;
        int n = idx - k * NO;
        g_w2t[idx] = W2[n * KH + k];            // write coalesced
    }
}

// -------- stage A: per-node projections u1 = h@W1[:, :128].T, u2 = h@W1[:,128:].T --------
__global__ void __launch_bounds__(256) node_proj(const float* __restrict__ h,
                                                 const float* __restrict__ W1) {
    extern __shared__ float sm[];
    float* hsA = sm;                    // 32*128
    float* w1s = sm + N_ * DH_;         // 64*LDW1

    int b  = blockIdx.y;
    int j0 = blockIdx.x * JTILE;
    int tid = threadIdx.x;

    for (int i = tid; i < N_ * DH_; i += 256)
        hsA[i] = h[(size_t)b * N_ * DH_ + i];
    for (int i = tid; i < JTILE * 256; i += 256) {
        int r = i >> 8, c = i & 255;
        w1s[r * LDW1 + c] = W1[(size_t)(j0 + r) * 256 + c];
    }
    __syncthreads();

    int jl = tid & 63;      // warp-aligned: lanes have distinct jl -> stride-257 conflict-free
    int ng = tid >> 6;      // node group (8 nodes)
    float acc1[8], acc2[8];
#pragma unroll
    for (int i = 0; i < 8; i++) { acc1[i] = 0.f; acc2[i] = 0.f; }

    const float* w1row = &w1s[jl * LDW1];
    const float* hbase = &hsA[ng * 8 * DH_];
#pragma unroll 4
    for (int k = 0; k < DH_; k++) {
        float wa = w1row[k];
        float wb = w1row[k + 128];
#pragma unroll
        for (int nn = 0; nn < 8; nn++) {
            float hv = hbase[nn * DH_ + k];     // broadcast within warp
            acc1[nn] = fmaf(wa, hv, acc1[nn]);
            acc2[nn] = fmaf(wb, hv, acc2[nn]);
        }
    }
    int j = j0 + jl;
#pragma unroll
    for (int nn = 0; nn < 8; nn++) {
        int n = ng * 8 + nn;
        g_u[(size_t)(b * N_ + n) * KH + j] = acc1[nn];
        g_u[(size_t)B_ * N_ * KH + (size_t)(b * N_ + n) * KH + j] = acc2[nn];
    }
}

// -------- stage B: fused hidden build + GEMM2 (f32x2) + payoff einsum --------
__global__ void __launch_bounds__(256) edge_gemm(const float* __restrict__ b1,
                                                 const float* __restrict__ b2,
                                                 float* __restrict__ out) {
    extern __shared__ float sm[];
    float* hs  = sm;                        // MROWS * LDH
    float* w2s = sm + MROWS * LDH;          // KH * NO  (reused as Ps after GEMM)
    float* Ps  = w2s;
    __shared__ int s_ef[ETILE], s_et[ETILE];

    int b   = blockIdx.y;
    int e0  = blockIdx.x * ETILE;
    int tid = threadIdx.x;

    if (tid < ETILE) { s_ef[tid] = g_ef[e0 + tid]; s_et[tid] = g_et[e0 + tid]; }
    for (int i = tid; i < KH * NO; i += 256) w2s[i] = g_w2t[i];   // coalesced both sides
    __syncthreads();

    // build h tile: rows 0..61 = s0 (u1[f]+u2[t]), rows 62..123 = s1 (u1[t]+u2[f])
    const float* u1b = &g_u[(size_t)(b * N_) * KH];
    const float* u2b = &g_u[(size_t)B_ * N_ * KH + (size_t)(b * N_) * KH];
    float b1k = b1[tid];                    // tid == k
#pragma unroll 4
    for (int m = 0; m < 2 * ETILE; m++) {
        int el = (m < ETILE) ? m : m - ETILE;
        int nf, nt;
        if (m < ETILE) { nf = s_ef[el]; nt = s_et[el]; }
        else           { nf = s_et[el]; nt = s_ef[el]; }
        float v = u1b[nf * KH + tid] + u2b[nt * KH + tid] + b1k;
        hs[m * LDH + tid] = fmaxf(v, 0.f);
    }
#pragma unroll
    for (int m = 2 * ETILE; m < MROWS; m++) hs[m * LDH + tid] = 0.f;  // pad rows
    __syncthreads();

    // GEMM: M=128, N=96, K=256; thread tile 4 rows x 12 cols (6 f32x2)
    int tn = tid & 7;       // column group: cols tn*12 .. tn*12+11
    int tm = tid >> 3;      // row group:    rows tm*4 .. tm*4+3
    unsigned long long acc[4][6];
#pragma unroll
    for (int r = 0; r < 4; r++)
#pragma unroll
        for (int q = 0; q < 6; q++) acc[r][q] = 0ull;

    const float* ar = &hs[(tm * 4) * LDH];
    const unsigned long long* wbase =
        reinterpret_cast<const unsigned long long*>(&w2s[tn * 12]);  // 48B-aligned

#pragma unroll 4
    for (int k = 0; k < KH; k++) {
        unsigned long long w[6];
        const unsigned long long* wk = wbase + (size_t)k * (NO / 2);
#pragma unroll
        for (int q = 0; q < 6; q++) w[q] = wk[q];     // LDS.64, banks {0,12,24,4,16,28,8,20}
#pragma unroll
        for (int r = 0; r < 4; r++) {
            unsigned long long A = pk2(ar[r * LDH + k]);  // 4 tm-banks 0/4/8/12 apart
#pragma unroll
            for (int q = 0; q < 6; q++) ffma2(acc[r][q], A, w[q]);
        }
    }

    // epilogue: + b2, unpack
    const float2* b2v = reinterpret_cast<const float2*>(b2);
    float2 pv[4][6];
#pragma unroll
    for (int r = 0; r < 4; r++)
#pragma unroll
        for (int q = 0; q < 6; q++) {
            float2 v = upk(acc[r][q]);
            float2 bb = b2v[tn * 6 + q];
            v.x += bb.x; v.y += bb.y;
            pv[r][q] = v;
        }

    __syncthreads();    // all threads done reading w2s/hs
#pragma unroll
    for (int r = 0; r < 4; r++) {
        int m = tm * 4 + r;
        if (m < 2 * ETILE) {
#pragma unroll
            for (int q = 0; q < 6; q++) {
                Ps[m * LDP + tn * 12 + 2 * q]     = pv[r][q].x;
                Ps[m * LDP + tn * 12 + 2 * q + 1] = pv[r][q].y;
            }
        }
    }
    __syncthreads();

    // payoff: out[b,e,i,j] = 0.5*( sum_r P0[24r+i]*P0[24r+12+j] + sum_r P1[24r+j]*P1[24r+12+i] )
    for (int pr = tid; pr < ETILE * AOUT; pr += 256) {
        int el = pr / AOUT;
        int i  = pr - el * AOUT;
        const float* P0 = &Ps[el * LDP];
        const float* P1 = &Ps[(ETILE + el) * LDP];
        float a0[4], a1[4];
#pragma unroll
        for (int r = 0; r < 4; r++) {
            a0[r] = P0[24 * r + i];
            a1[r] = P1[24 * r + 12 + i];
        }
        float res[12];
#pragma unroll
        for (int j = 0; j < 12; j++) {
            float s = 0.f;
#pragma unroll
            for (int r = 0; r < 4; r++)
                s = fmaf(a0[r], P0[24 * r + 12 + j], fmaf(a1[r], P1[24 * r + j], s));
            res[j] = 0.5f * s;
        }
        float4* op = reinterpret_cast<float4*>(
            out + ((size_t)(b * E_ + e0 + el) * AOUT + i) * AOUT);
        op[0] = make_float4(res[0], res[1], res[2],  res[3]);
        op[1] = make_float4(res[4], res[5], res[6],  res[7]);
        op[2] = make_float4(res[8], res[9], res[10], res[11]);
    }
}

// -------- launch --------
extern "C" void kernel_launch(void* const* d_in, const int* in_sizes, int n_in,
                              void* d_out, int out_size) {
    const float* h  = (const float*)d_in[0];
    const float* W1 = (const float*)d_in[1];
    const float* b1 = (const float*)d_in[2];
    const float* W2 = (const float*)d_in[3];
    const float* b2 = (const float*)d_in[4];
    const int*   ef = (const int*)d_in[5];
    const int*   et = (const int*)d_in[6];
    float* out = (float*)d_out;

    const int SMEM_A = (N_ * DH_ + JTILE * LDW1) * 4;      // 82,176 B
    const int SMEM_B = (MROWS * LDH + KH * NO) * 4;        // 229,888 B

    cudaFuncSetAttribute(node_proj, cudaFuncAttributeMaxDynamicSharedMemorySize, SMEM_A);
    cudaFuncSetAttribute(edge_gemm, cudaFuncAttributeMaxDynamicSharedMemorySize, SMEM_B);

    prep_edges<<<1, 256>>>(ef, et);
    transpose_w2<<<(KH * NO + 255) / 256, 256>>>(W2);
    node_proj<<<dim3(KH / JTILE, B_), 256, SMEM_A>>>(h, W1);
    edge_gemm<<<dim3(E_ / ETILE, B_), 256, SMEM_B>>>(b1, b2, out);
}